// round 3
// baseline (speedup 1.0000x reference)
#include <cuda_runtime.h>

// ---------------------------------------------------------------------------
// GraphSAGE 2-layer, N=100000 nodes, E edges, d: 128 -> 128 -> 64, fp32.
//   h   = relu( mean_agg(x) @ W1_l + b1 + x @ W1_r )
//   out = mean_agg(h @ W2_l) + b2 + h @ W2_r     (mean/matmul commuted, layer 2)
// ---------------------------------------------------------------------------

#define NN 100000

constexpr size_t DEG   = 0;
constexpr size_t AGG1  = 102400;                         // node feature sums, layer 1 (N x 128)
constexpr size_t AGG2  = AGG1 + (size_t)NN * 128;        // layer-2 sums (N x 64)
constexpr size_t ZEROF = AGG2 + (size_t)NN * 64;         // floats that must be zeroed
constexpr size_t INVD  = ZEROF;                          // 1/max(deg,1)
constexpr size_t HBUF  = INVD + 102400;                  // h (N x 128)
constexpr size_t TR2   = HBUF + (size_t)NN * 128;        // [t2 | r2] (N x 128): cols 0..63 = h@W2_l, 64..127 = h@W2_r
constexpr size_t TOTAL = TR2 + (size_t)NN * 128;

__device__ float g_scratch[TOTAL];
__device__ int   g_idx64;

// ---------------------------------------------------------------------------
// Detect whether edge_index arrived as int64 or int32 (JAX x64 ambiguity).
// int64 little-endian with values < 2^17 => all odd 32-bit words are zero.
// ---------------------------------------------------------------------------
__global__ void detect_kernel(const void* ei) {
    const int* w = (const int*)ei;
    int lane = threadIdx.x;
    int nz = 0;
    for (int i = lane * 2 + 1; i < 512; i += 64) nz |= (w[i] != 0);
    unsigned m = __ballot_sync(0xffffffffu, nz);
    if (lane == 0) g_idx64 = (m == 0) ? 1 : 0;
}

__global__ void zero_kernel() {
    size_t i = (size_t)blockIdx.x * blockDim.x + threadIdx.x;   // float4 index
    if (i < ZEROF / 4) {
        ((float4*)g_scratch)[i] = make_float4(0.f, 0.f, 0.f, 0.f);
    }
}

// ---------------------------------------------------------------------------
// Layer-1 aggregation: agg1[dst] += x[src] (128 floats, one warp per edge),
// plus degree count (lane 0).
// ---------------------------------------------------------------------------
__global__ void agg1_kernel(const float* __restrict__ x, const void* __restrict__ ei, int E) {
    size_t tid = (size_t)blockIdx.x * blockDim.x + threadIdx.x;
    int gw = (int)(tid >> 5);           // one warp = one edge (uniform across warp)
    if (gw >= E) return;
    int lane = threadIdx.x & 31;
    int sv = 0, dv = 0;
    if (lane == 0) {
        if (g_idx64) {
            const long long* p = (const long long*)ei;
            sv = (int)p[gw]; dv = (int)p[(size_t)E + gw];
        } else {
            const int* p = (const int*)ei;
            sv = p[gw]; dv = p[(size_t)E + gw];
        }
    }
    int src = __shfl_sync(0xffffffffu, sv, 0);
    int dst = __shfl_sync(0xffffffffu, dv, 0);
    float4 v = ((const float4*)(x + (size_t)src * 128))[lane];
    float* a = g_scratch + AGG1 + (size_t)dst * 128 + lane * 4;
    asm volatile("red.global.add.v4.f32 [%0], {%1,%2,%3,%4};"
                 :: "l"(a), "f"(v.x), "f"(v.y), "f"(v.z), "f"(v.w) : "memory");
    if (lane == 0) atomicAdd(&g_scratch[DEG + dst], 1.0f);
}

__global__ void invdeg_kernel() {
    int i = blockIdx.x * blockDim.x + threadIdx.x;
    if (i < NN) {
        float d = g_scratch[DEG + i];
        g_scratch[INVD + i] = 1.0f / fmaxf(d, 1.0f);
    }
}

// ---------------------------------------------------------------------------
// Layer-2 aggregation: agg2[dst] += t2[src] (64 floats, 16 lanes per edge).
// t2 lives in cols 0..63 of TR2.
// ---------------------------------------------------------------------------
__global__ void agg2_kernel(const void* __restrict__ ei, int E) {
    size_t tid = (size_t)blockIdx.x * blockDim.x + threadIdx.x;
    int e = (int)(tid >> 4);
    int lane = threadIdx.x & 31;
    bool valid = (e < E);
    int sv = 0, dv = 0;
    if (valid && (lane & 15) == 0) {
        if (g_idx64) {
            const long long* p = (const long long*)ei;
            sv = (int)p[e]; dv = (int)p[(size_t)E + e];
        } else {
            const int* p = (const int*)ei;
            sv = p[e]; dv = p[(size_t)E + e];
        }
    }
    int src = __shfl_sync(0xffffffffu, sv, lane & 16);
    int dst = __shfl_sync(0xffffffffu, dv, lane & 16);
    if (valid) {
        int part = lane & 15;
        float4 v = ((const float4*)(g_scratch + TR2 + (size_t)src * 128))[part];
        float* a = g_scratch + AGG2 + (size_t)dst * 64 + part * 4;
        asm volatile("red.global.add.v4.f32 [%0], {%1,%2,%3,%4};"
                     :: "l"(a), "f"(v.x), "f"(v.y), "f"(v.z), "f"(v.w) : "memory");
    }
}

// ---------------------------------------------------------------------------
// GEMM 1: h = relu( (agg1 * invdeg) @ W1_l + x @ W1_r + b1 )
//   M = NN, N = 128, K = 128 per operand pair (two pairs accumulated).
//   128x128 block tile, BK=16, 256 threads, 8x8 register tile.
// ---------------------------------------------------------------------------
__global__ __launch_bounds__(256) void gemm1_kernel(
    const float* __restrict__ x, const float* __restrict__ W1l,
    const float* __restrict__ b1, const float* __restrict__ W1r) {
    __shared__ float As[16][132];
    __shared__ float Bs[16][128];
    int t = threadIdx.x;
    int row0 = blockIdx.x * 128;
    int tx = t & 15, ty = t >> 4;

    float acc[8][8];
#pragma unroll
    for (int i = 0; i < 8; i++)
#pragma unroll
        for (int j = 0; j < 8; j++) acc[i][j] = 0.f;

    const float* agg1 = g_scratch + AGG1;
    const float* invd = g_scratch + INVD;

    for (int pair = 0; pair < 2; pair++) {
        const float* A = pair ? x : agg1;
        const float* B = pair ? W1r : W1l;
        for (int kt = 0; kt < 128; kt += 16) {
#pragma unroll
            for (int l = 0; l < 2; l++) {             // A tile: 128 rows x 16 k
                int q = t + l * 256;
                int ar = q >> 2;
                int ak = (q & 3) * 4;
                int grow = row0 + ar;
                float4 v = make_float4(0.f, 0.f, 0.f, 0.f);
                if (grow < NN) {
                    v = *(const float4*)(A + (size_t)grow * 128 + kt + ak);
                    if (pair == 0) {
                        float s = invd[grow];
                        v.x *= s; v.y *= s; v.z *= s; v.w *= s;
                    }
                }
                As[ak + 0][ar] = v.x; As[ak + 1][ar] = v.y;
                As[ak + 2][ar] = v.z; As[ak + 3][ar] = v.w;
            }
#pragma unroll
            for (int l = 0; l < 2; l++) {             // B tile: 16 k x 128 n
                int q = t + l * 256;
                int bk = q >> 5;
                int bn = (q & 31) * 4;
                *(float4*)&Bs[bk][bn] = *(const float4*)(B + (size_t)(kt + bk) * 128 + bn);
            }
            __syncthreads();
#pragma unroll
            for (int k = 0; k < 16; k++) {
                float4 a0 = *(float4*)&As[k][ty * 8];
                float4 a1 = *(float4*)&As[k][ty * 8 + 4];
                float4 b0 = *(float4*)&Bs[k][tx * 8];
                float4 b1v = *(float4*)&Bs[k][tx * 8 + 4];
                float a[8] = {a0.x, a0.y, a0.z, a0.w, a1.x, a1.y, a1.z, a1.w};
                float b[8] = {b0.x, b0.y, b0.z, b0.w, b1v.x, b1v.y, b1v.z, b1v.w};
#pragma unroll
                for (int i = 0; i < 8; i++)
#pragma unroll
                    for (int j = 0; j < 8; j++) acc[i][j] += a[i] * b[j];
            }
            __syncthreads();
        }
    }

    float* h = g_scratch + HBUF;
#pragma unroll
    for (int i = 0; i < 8; i++) {
        int r = row0 + ty * 8 + i;
        if (r < NN) {
#pragma unroll
            for (int j = 0; j < 8; j += 4) {
                int c = tx * 8 + j;
                float4 o;
                o.x = fmaxf(acc[i][j + 0] + b1[c + 0], 0.f);
                o.y = fmaxf(acc[i][j + 1] + b1[c + 1], 0.f);
                o.z = fmaxf(acc[i][j + 2] + b1[c + 2], 0.f);
                o.w = fmaxf(acc[i][j + 3] + b1[c + 3], 0.f);
                *(float4*)(h + (size_t)r * 128 + c) = o;
            }
        }
    }
}

// ---------------------------------------------------------------------------
// GEMM 2: TR2 = h @ [W2_l | W2_r]   (M = NN, N = 128, K = 128)
// ---------------------------------------------------------------------------
__global__ __launch_bounds__(256) void gemm2_kernel(
    const float* __restrict__ W2l, const float* __restrict__ W2r) {
    __shared__ float As[16][132];
    __shared__ float Bs[16][128];
    int t = threadIdx.x;
    int row0 = blockIdx.x * 128;
    int tx = t & 15, ty = t >> 4;

    float acc[8][8];
#pragma unroll
    for (int i = 0; i < 8; i++)
#pragma unroll
        for (int j = 0; j < 8; j++) acc[i][j] = 0.f;

    const float* h = g_scratch + HBUF;

    for (int kt = 0; kt < 128; kt += 16) {
#pragma unroll
        for (int l = 0; l < 2; l++) {
            int q = t + l * 256;
            int ar = q >> 2;
            int ak = (q & 3) * 4;
            int grow = row0 + ar;
            float4 v = make_float4(0.f, 0.f, 0.f, 0.f);
            if (grow < NN) v = *(const float4*)(h + (size_t)grow * 128 + kt + ak);
            As[ak + 0][ar] = v.x; As[ak + 1][ar] = v.y;
            As[ak + 2][ar] = v.z; As[ak + 3][ar] = v.w;
        }
#pragma unroll
        for (int l = 0; l < 2; l++) {
            int q = t + l * 256;
            int bk = q >> 5;
            int bn = (q & 31) * 4;
            float4 v;
            if (bn < 64) v = *(const float4*)(W2l + (size_t)(kt + bk) * 64 + bn);
            else         v = *(const float4*)(W2r + (size_t)(kt + bk) * 64 + (bn - 64));
            *(float4*)&Bs[bk][bn] = v;
        }
        __syncthreads();
#pragma unroll
        for (int k = 0; k < 16; k++) {
            float4 a0 = *(float4*)&As[k][ty * 8];
            float4 a1 = *(float4*)&As[k][ty * 8 + 4];
            float4 b0 = *(float4*)&Bs[k][tx * 8];
            float4 b1v = *(float4*)&Bs[k][tx * 8 + 4];
            float a[8] = {a0.x, a0.y, a0.z, a0.w, a1.x, a1.y, a1.z, a1.w};
            float b[8] = {b0.x, b0.y, b0.z, b0.w, b1v.x, b1v.y, b1v.z, b1v.w};
#pragma unroll
            for (int i = 0; i < 8; i++)
#pragma unroll
                for (int j = 0; j < 8; j++) acc[i][j] += a[i] * b[j];
        }
        __syncthreads();
    }

    float* tr2 = g_scratch + TR2;
#pragma unroll
    for (int i = 0; i < 8; i++) {
        int r = row0 + ty * 8 + i;
        if (r < NN) {
#pragma unroll
            for (int j = 0; j < 8; j += 4) {
                int c = tx * 8 + j;
                float4 o = make_float4(acc[i][j], acc[i][j + 1], acc[i][j + 2], acc[i][j + 3]);
                *(float4*)(tr2 + (size_t)r * 128 + c) = o;
            }
        }
    }
}

// ---------------------------------------------------------------------------
// Final: out[i][n] = agg2[i][n] * invdeg[i] + b2[n] + r2[i][n]
// ---------------------------------------------------------------------------
__global__ void final_kernel(const float* __restrict__ b2, float* __restrict__ out) {
    int idx = blockIdx.x * blockDim.x + threadIdx.x;    // over NN*16 float4s
    if (idx < NN * 16) {
        int i = idx >> 4;
        int n4 = (idx & 15) * 4;
        float s = g_scratch[INVD + i];
        float4 a = *(const float4*)(g_scratch + AGG2 + (size_t)i * 64 + n4);
        float4 r = *(const float4*)(g_scratch + TR2 + (size_t)i * 128 + 64 + n4);
        float4 bb = *(const float4*)(b2 + n4);
        float4 o;
        o.x = a.x * s + bb.x + r.x;
        o.y = a.y * s + bb.y + r.y;
        o.z = a.z * s + bb.z + r.z;
        o.w = a.w * s + bb.w + r.w;
        *(float4*)(out + (size_t)i * 64 + n4) = o;
    }
}

extern "C" void kernel_launch(void* const* d_in, const int* in_sizes, int n_in,
                              void* d_out, int out_size) {
    const float* x   = (const float*)d_in[0];
    const float* W1l = (const float*)d_in[1];
    const float* b1  = (const float*)d_in[2];
    const float* W1r = (const float*)d_in[3];
    const float* W2l = (const float*)d_in[4];
    const float* b2  = (const float*)d_in[5];
    const float* W2r = (const float*)d_in[6];
    const void*  ei  = d_in[7];
    int E = in_sizes[7] / 2;
    float* out = (float*)d_out;

    detect_kernel<<<1, 32>>>(ei);

    {
        long long n4 = (long long)(ZEROF / 4);
        int blocks = (int)((n4 + 255) / 256);
        zero_kernel<<<blocks, 256>>>();
    }

    {
        long long threads = (long long)E * 32;
        int blocks = (int)((threads + 255) / 256);
        agg1_kernel<<<blocks, 256>>>(x, ei, E);
    }

    invdeg_kernel<<<(NN + 255) / 256, 256>>>();

    gemm1_kernel<<<(NN + 127) / 128, 256>>>(x, W1l, b1, W1r);
    gemm2_kernel<<<(NN + 127) / 128, 256>>>(W2l, W2r);

    {
        long long threads = (long long)E * 16;
        int blocks = (int)((threads + 255) / 256);
        agg2_kernel<<<blocks, 256>>>(ei, E);
    }

    final_kernel<<<(NN * 16 + 255) / 256, 256>>>(b2, out);
}

// round 5
// speedup vs baseline: 2.2350x; 2.2350x over previous
#include <cuda_runtime.h>

// ---------------------------------------------------------------------------
// GraphSAGE 2-layer, N=100000 nodes, E edges, d: 128 -> 128 -> 64, fp32.
//   h   = relu( mean_agg(x) @ W1_l + b1 + x @ W1_r )
//   out = mean_agg(h @ W2_l) + b2 + h @ W2_r     (mean/matmul commuted)
// Aggregation via CSR (build once per call): gather-side reduction, no
// float atomics. All persistent device state is fully rewritten each call
// (graph-replay idempotent).
// ---------------------------------------------------------------------------

#define NN 100000
#define EMAX 3200000
#define NB_SCAN 98            // ceil(NN/1024)

// float scratch
constexpr size_t AGG1  = 0;                              // mean_agg(x)   (N x 128)
constexpr size_t HBUF  = AGG1 + (size_t)NN * 128;        // h             (N x 128)
constexpr size_t TR2   = HBUF + (size_t)NN * 128;        // [t2|r2]       (N x 128)
constexpr size_t FTOT  = TR2 + (size_t)NN * 128;
__device__ float g_f[FTOT];

// int scratch  (CNT and TMP MUST be contiguous: one zeroing pass covers both)
constexpr size_t ROWPTR = 0;                             // NN+1
constexpr size_t CNT    = 100004;                        // NN
constexpr size_t TMP    = CNT + NN;                      // NN   (= 200004, contiguous!)
constexpr size_t BSUM   = 300012;                        // 128
constexpr size_t SORTED = 300160;                        // EMAX
__device__ int g_i[SORTED + EMAX];
__device__ int g_idx64;

// ---------------------------------------------------------------------------
// int64 vs int32 edge_index detection (values < 2^17 => odd words all zero)
// ---------------------------------------------------------------------------
__global__ void detect_kernel(const void* ei) {
    const int* w = (const int*)ei;
    int lane = threadIdx.x;
    int nz = 0;
    for (int i = lane * 2 + 1; i < 512; i += 64) nz |= (w[i] != 0);
    unsigned m = __ballot_sync(0xffffffffu, nz);
    if (lane == 0) g_idx64 = (m == 0) ? 1 : 0;
}

__global__ void zero_int_kernel() {
    int i = blockIdx.x * blockDim.x + threadIdx.x;
    if (i < 2 * NN) g_i[CNT + i] = 0;     // covers CNT[0..NN) and TMP[0..NN) exactly
}

__device__ __forceinline__ void load_edge(const void* ei, int e, int E, int& src, int& dst) {
    if (g_idx64) {
        const long long* p = (const long long*)ei;
        src = (int)p[e]; dst = (int)p[(size_t)E + e];
    } else {
        const int* p = (const int*)ei;
        src = p[e]; dst = p[(size_t)E + e];
    }
}

__global__ void hist_kernel(const void* __restrict__ ei, int E) {
    int e = blockIdx.x * blockDim.x + threadIdx.x;
    if (e >= E) return;
    int dst;
    if (g_idx64) dst = (int)((const long long*)ei)[(size_t)E + e];
    else         dst = ((const int*)ei)[(size_t)E + e];
    atomicAdd(&g_i[CNT + dst], 1);
}

// Block-level inclusive scan of CNT -> rowptr[i+1], block totals -> BSUM
__global__ void scan_a_kernel() {
    __shared__ int s[1024];
    int t = threadIdx.x;
    int i = blockIdx.x * 1024 + t;
    int v = (i < NN) ? g_i[CNT + i] : 0;
    s[t] = v;
    __syncthreads();
#pragma unroll
    for (int off = 1; off < 1024; off <<= 1) {
        int u = (t >= off) ? s[t - off] : 0;
        __syncthreads();
        s[t] += u;
        __syncthreads();
    }
    if (i < NN) g_i[ROWPTR + i + 1] = s[t];
    if (t == 1023) g_i[BSUM + blockIdx.x] = s[1023];
}

// Exclusive scan of 98 block sums (single block)
__global__ void scan_b_kernel() {
    __shared__ int s[128];
    int t = threadIdx.x;
    int v = (t < NB_SCAN) ? g_i[BSUM + t] : 0;
    s[t] = v;
    __syncthreads();
#pragma unroll
    for (int off = 1; off < 128; off <<= 1) {
        int u = (t >= off) ? s[t - off] : 0;
        __syncthreads();
        s[t] += u;
        __syncthreads();
    }
    if (t < NB_SCAN) g_i[BSUM + t] = s[t] - v;   // exclusive
}

__global__ void scan_c_kernel() {
    int i = blockIdx.x * blockDim.x + threadIdx.x;
    if (i < NN) g_i[ROWPTR + i + 1] += g_i[BSUM + (i >> 10)];
    if (i == 0) g_i[ROWPTR] = 0;
}

__global__ void scatter_kernel(const void* __restrict__ ei, int E) {
    int e = blockIdx.x * blockDim.x + threadIdx.x;
    if (e >= E) return;
    int src, dst;
    load_edge(ei, e, E, src, dst);
    int pos = g_i[ROWPTR + dst] + atomicAdd(&g_i[TMP + dst], 1);
    g_i[SORTED + pos] = src;
}

// ---------------------------------------------------------------------------
// Layer-1 aggregation: one warp per dst node, register accumulation,
// writes the MEAN row (scale folded in). Unroll-4 edge loop for MLP.
// ---------------------------------------------------------------------------
__global__ __launch_bounds__(256) void agg1_kernel(const float* __restrict__ x) {
    int node = (int)(((size_t)blockIdx.x * blockDim.x + threadIdx.x) >> 5);
    if (node >= NN) return;
    int lane = threadIdx.x & 31;
    int beg = g_i[ROWPTR + node];
    int end = g_i[ROWPTR + node + 1];
    const int* srt = g_i + SORTED;
    float4 acc = make_float4(0.f, 0.f, 0.f, 0.f);
    int e = beg;
    for (; e + 4 <= end; e += 4) {
        int s0 = srt[e], s1 = srt[e + 1], s2 = srt[e + 2], s3 = srt[e + 3];
        float4 v0 = ((const float4*)(x + (size_t)s0 * 128))[lane];
        float4 v1 = ((const float4*)(x + (size_t)s1 * 128))[lane];
        float4 v2 = ((const float4*)(x + (size_t)s2 * 128))[lane];
        float4 v3 = ((const float4*)(x + (size_t)s3 * 128))[lane];
        acc.x += (v0.x + v1.x) + (v2.x + v3.x);
        acc.y += (v0.y + v1.y) + (v2.y + v3.y);
        acc.z += (v0.z + v1.z) + (v2.z + v3.z);
        acc.w += (v0.w + v1.w) + (v2.w + v3.w);
    }
    for (; e < end; e++) {
        float4 v = ((const float4*)(x + (size_t)srt[e] * 128))[lane];
        acc.x += v.x; acc.y += v.y; acc.z += v.z; acc.w += v.w;
    }
    float sc = 1.0f / fmaxf((float)(end - beg), 1.0f);
    ((float4*)(g_f + AGG1 + (size_t)node * 128))[lane] =
        make_float4(acc.x * sc, acc.y * sc, acc.z * sc, acc.w * sc);
}

// ---------------------------------------------------------------------------
// GEMM 1: h = relu( agg1 @ W1_l + x @ W1_r + b1 )   (agg1 already the mean)
//   128x128 block tile, BK=16, 256 threads, 8x8 register tile.
// ---------------------------------------------------------------------------
__global__ __launch_bounds__(256) void gemm1_kernel(
    const float* __restrict__ x, const float* __restrict__ W1l,
    const float* __restrict__ b1, const float* __restrict__ W1r) {
    __shared__ float As[16][132];
    __shared__ float Bs[16][128];
    int t = threadIdx.x;
    int row0 = blockIdx.x * 128;
    int tx = t & 15, ty = t >> 4;

    float acc[8][8];
#pragma unroll
    for (int i = 0; i < 8; i++)
#pragma unroll
        for (int j = 0; j < 8; j++) acc[i][j] = 0.f;

    const float* agg1 = g_f + AGG1;

    for (int pair = 0; pair < 2; pair++) {
        const float* A = pair ? x : agg1;
        const float* B = pair ? W1r : W1l;
        for (int kt = 0; kt < 128; kt += 16) {
#pragma unroll
            for (int l = 0; l < 2; l++) {
                int q = t + l * 256;
                int ar = q >> 2;
                int ak = (q & 3) * 4;
                int grow = row0 + ar;
                float4 v = make_float4(0.f, 0.f, 0.f, 0.f);
                if (grow < NN) v = *(const float4*)(A + (size_t)grow * 128 + kt + ak);
                As[ak + 0][ar] = v.x; As[ak + 1][ar] = v.y;
                As[ak + 2][ar] = v.z; As[ak + 3][ar] = v.w;
            }
#pragma unroll
            for (int l = 0; l < 2; l++) {
                int q = t + l * 256;
                int bk = q >> 5;
                int bn = (q & 31) * 4;
                *(float4*)&Bs[bk][bn] = *(const float4*)(B + (size_t)(kt + bk) * 128 + bn);
            }
            __syncthreads();
#pragma unroll
            for (int k = 0; k < 16; k++) {
                float4 a0 = *(float4*)&As[k][ty * 8];
                float4 a1 = *(float4*)&As[k][ty * 8 + 4];
                float4 b0 = *(float4*)&Bs[k][tx * 8];
                float4 b1v = *(float4*)&Bs[k][tx * 8 + 4];
                float a[8] = {a0.x, a0.y, a0.z, a0.w, a1.x, a1.y, a1.z, a1.w};
                float b[8] = {b0.x, b0.y, b0.z, b0.w, b1v.x, b1v.y, b1v.z, b1v.w};
#pragma unroll
                for (int i = 0; i < 8; i++)
#pragma unroll
                    for (int j = 0; j < 8; j++) acc[i][j] += a[i] * b[j];
            }
            __syncthreads();
        }
    }

    float* h = g_f + HBUF;
#pragma unroll
    for (int i = 0; i < 8; i++) {
        int r = row0 + ty * 8 + i;
        if (r < NN) {
#pragma unroll
            for (int j = 0; j < 8; j += 4) {
                int c = tx * 8 + j;
                float4 o;
                o.x = fmaxf(acc[i][j + 0] + b1[c + 0], 0.f);
                o.y = fmaxf(acc[i][j + 1] + b1[c + 1], 0.f);
                o.z = fmaxf(acc[i][j + 2] + b1[c + 2], 0.f);
                o.w = fmaxf(acc[i][j + 3] + b1[c + 3], 0.f);
                *(float4*)(h + (size_t)r * 128 + c) = o;
            }
        }
    }
}

// ---------------------------------------------------------------------------
// GEMM 2: TR2 = h @ [W2_l | W2_r]   (M = NN, N = 128, K = 128)
// ---------------------------------------------------------------------------
__global__ __launch_bounds__(256) void gemm2_kernel(
    const float* __restrict__ W2l, const float* __restrict__ W2r) {
    __shared__ float As[16][132];
    __shared__ float Bs[16][128];
    int t = threadIdx.x;
    int row0 = blockIdx.x * 128;
    int tx = t & 15, ty = t >> 4;

    float acc[8][8];
#pragma unroll
    for (int i = 0; i < 8; i++)
#pragma unroll
        for (int j = 0; j < 8; j++) acc[i][j] = 0.f;

    const float* h = g_f + HBUF;

    for (int kt = 0; kt < 128; kt += 16) {
#pragma unroll
        for (int l = 0; l < 2; l++) {
            int q = t + l * 256;
            int ar = q >> 2;
            int ak = (q & 3) * 4;
            int grow = row0 + ar;
            float4 v = make_float4(0.f, 0.f, 0.f, 0.f);
            if (grow < NN) v = *(const float4*)(h + (size_t)grow * 128 + kt + ak);
            As[ak + 0][ar] = v.x; As[ak + 1][ar] = v.y;
            As[ak + 2][ar] = v.z; As[ak + 3][ar] = v.w;
        }
#pragma unroll
        for (int l = 0; l < 2; l++) {
            int q = t + l * 256;
            int bk = q >> 5;
            int bn = (q & 31) * 4;
            float4 v;
            if (bn < 64) v = *(const float4*)(W2l + (size_t)(kt + bk) * 64 + bn);
            else         v = *(const float4*)(W2r + (size_t)(kt + bk) * 64 + (bn - 64));
            *(float4*)&Bs[bk][bn] = v;
        }
        __syncthreads();
#pragma unroll
        for (int k = 0; k < 16; k++) {
            float4 a0 = *(float4*)&As[k][ty * 8];
            float4 a1 = *(float4*)&As[k][ty * 8 + 4];
            float4 b0 = *(float4*)&Bs[k][tx * 8];
            float4 b1v = *(float4*)&Bs[k][tx * 8 + 4];
            float a[8] = {a0.x, a0.y, a0.z, a0.w, a1.x, a1.y, a1.z, a1.w};
            float b[8] = {b0.x, b0.y, b0.z, b0.w, b1v.x, b1v.y, b1v.z, b1v.w};
#pragma unroll
            for (int i = 0; i < 8; i++)
#pragma unroll
                for (int j = 0; j < 8; j++) acc[i][j] += a[i] * b[j];
        }
        __syncthreads();
    }

    float* tr2 = g_f + TR2;
#pragma unroll
    for (int i = 0; i < 8; i++) {
        int r = row0 + ty * 8 + i;
        if (r < NN) {
#pragma unroll
            for (int j = 0; j < 8; j += 4) {
                int c = tx * 8 + j;
                *(float4*)(tr2 + (size_t)r * 128 + c) =
                    make_float4(acc[i][j], acc[i][j + 1], acc[i][j + 2], acc[i][j + 3]);
            }
        }
    }
}

// ---------------------------------------------------------------------------
// Layer-2 aggregation fused with epilogue:
//   out[i] = mean_{j in N(i)} t2[j] + b2 + r2[i]
// One warp per node; lane owns a float2 (64 cols).
// ---------------------------------------------------------------------------
__global__ __launch_bounds__(256) void agg2_kernel(const float* __restrict__ b2,
                                                   float* __restrict__ out) {
    int node = (int)(((size_t)blockIdx.x * blockDim.x + threadIdx.x) >> 5);
    if (node >= NN) return;
    int lane = threadIdx.x & 31;
    int beg = g_i[ROWPTR + node];
    int end = g_i[ROWPTR + node + 1];
    const int* srt = g_i + SORTED;
    const float* t2 = g_f + TR2;
    float2 acc = make_float2(0.f, 0.f);
    int e = beg;
    for (; e + 4 <= end; e += 4) {
        int s0 = srt[e], s1 = srt[e + 1], s2 = srt[e + 2], s3 = srt[e + 3];
        float2 v0 = ((const float2*)(t2 + (size_t)s0 * 128))[lane];
        float2 v1 = ((const float2*)(t2 + (size_t)s1 * 128))[lane];
        float2 v2 = ((const float2*)(t2 + (size_t)s2 * 128))[lane];
        float2 v3 = ((const float2*)(t2 + (size_t)s3 * 128))[lane];
        acc.x += (v0.x + v1.x) + (v2.x + v3.x);
        acc.y += (v0.y + v1.y) + (v2.y + v3.y);
    }
    for (; e < end; e++) {
        float2 v = ((const float2*)(t2 + (size_t)srt[e] * 128))[lane];
        acc.x += v.x; acc.y += v.y;
    }
    float sc = 1.0f / fmaxf((float)(end - beg), 1.0f);
    float2 r = ((const float2*)(t2 + (size_t)node * 128 + 64))[lane];
    float2 bb = ((const float2*)b2)[lane];
    float2 o;
    o.x = acc.x * sc + bb.x + r.x;
    o.y = acc.y * sc + bb.y + r.y;
    ((float2*)(out + (size_t)node * 64))[lane] = o;
}

extern "C" void kernel_launch(void* const* d_in, const int* in_sizes, int n_in,
                              void* d_out, int out_size) {
    const float* x   = (const float*)d_in[0];
    const float* W1l = (const float*)d_in[1];
    const float* b1  = (const float*)d_in[2];
    const float* W1r = (const float*)d_in[3];
    const float* W2l = (const float*)d_in[4];
    const float* b2  = (const float*)d_in[5];
    const float* W2r = (const float*)d_in[6];
    const void*  ei  = d_in[7];
    int E = in_sizes[7] / 2;
    if (E > EMAX) E = EMAX;
    float* out = (float*)d_out;

    detect_kernel<<<1, 32>>>(ei);
    zero_int_kernel<<<(2 * NN + 255) / 256, 256>>>();
    hist_kernel<<<(E + 255) / 256, 256>>>(ei, E);
    scan_a_kernel<<<NB_SCAN, 1024>>>();
    scan_b_kernel<<<1, 128>>>();
    scan_c_kernel<<<(NN + 255) / 256, 256>>>();
    scatter_kernel<<<(E + 255) / 256, 256>>>(ei, E);

    agg1_kernel<<<(NN * 32 + 255) / 256, 256>>>(x);
    gemm1_kernel<<<(NN + 127) / 128, 256>>>(x, W1l, b1, W1r);
    gemm2_kernel<<<(NN + 127) / 128, 256>>>(W2l, W2r);
    agg2_kernel<<<(NN * 32 + 255) / 256, 256>>>(b2, out);
}

// round 7
// speedup vs baseline: 2.2548x; 1.0088x over previous
#include <cuda_runtime.h>

// ---------------------------------------------------------------------------
// GraphSAGE 2-layer, N=100000 nodes, E edges, d: 128 -> 128 -> 64, fp32.
//   h   = relu( mean_agg(x) @ W1_l + b1 + x @ W1_r )
//   out = mean_agg(h @ W2_l) + b2 + h @ W2_r     (mean/matmul commuted)
// CSR gather aggregation + packed f32x2 FFMA2 GEMMs (2x fp32 FMA/instr).
// All persistent device state fully rewritten each call (replay idempotent).
// R6: identical to R5 submission — R5 bench hit an infra "device busy" error
// before kernel execution; resubmitting for a clean FFMA2 measurement.
// ---------------------------------------------------------------------------

#define NN 100000
#define EMAX 3200000
#define NB_SCAN 98            // ceil(NN/1024)

// float scratch
constexpr size_t AGG1  = 0;                              // mean_agg(x)   (N x 128)
constexpr size_t HBUF  = AGG1 + (size_t)NN * 128;        // h             (N x 128)
constexpr size_t TR2   = HBUF + (size_t)NN * 128;        // [t2|r2]       (N x 128)
constexpr size_t FTOT  = TR2 + (size_t)NN * 128;
__device__ float g_f[FTOT];

// int scratch  (CNT and TMP contiguous: one zeroing pass covers both)
constexpr size_t ROWPTR = 0;                             // NN+1
constexpr size_t CNT    = 100004;                        // NN
constexpr size_t TMP    = CNT + NN;                      // NN (contiguous)
constexpr size_t BSUM   = 300012;                        // 128
constexpr size_t SORTED = 300160;                        // EMAX
__device__ int g_i[SORTED + EMAX];
__device__ int g_idx64;

// ---- packed fp32x2 helpers (sm_103a FFMA2 path, PTX-only) -----------------
__device__ __forceinline__ void fma2(unsigned long long& d,
                                     unsigned long long a,
                                     unsigned long long b) {
    asm("fma.rn.f32x2 %0, %1, %2, %0;" : "+l"(d) : "l"(a), "l"(b));
}
__device__ __forceinline__ unsigned long long pack2(float lo, float hi) {
    unsigned long long r;
    asm("mov.b64 %0, {%1, %2};" : "=l"(r) : "f"(lo), "f"(hi));
    return r;
}
__device__ __forceinline__ void unpack2(float& lo, float& hi, unsigned long long v) {
    asm("mov.b64 {%0, %1}, %2;" : "=f"(lo), "=f"(hi) : "l"(v));
}

// ---------------------------------------------------------------------------
// int64 vs int32 edge_index detection (values < 2^17 => odd words all zero)
// ---------------------------------------------------------------------------
__global__ void detect_kernel(const void* ei) {
    const int* w = (const int*)ei;
    int lane = threadIdx.x;
    int nz = 0;
    for (int i = lane * 2 + 1; i < 512; i += 64) nz |= (w[i] != 0);
    unsigned m = __ballot_sync(0xffffffffu, nz);
    if (lane == 0) g_idx64 = (m == 0) ? 1 : 0;
}

__global__ void zero_int_kernel() {
    int i = blockIdx.x * blockDim.x + threadIdx.x;
    if (i < 2 * NN) g_i[CNT + i] = 0;
}

__device__ __forceinline__ void load_edge(const void* ei, int e, int E, int& src, int& dst) {
    if (g_idx64) {
        const long long* p = (const long long*)ei;
        src = (int)p[e]; dst = (int)p[(size_t)E + e];
    } else {
        const int* p = (const int*)ei;
        src = p[e]; dst = p[(size_t)E + e];
    }
}

__global__ void hist_kernel(const void* __restrict__ ei, int E) {
    int e = blockIdx.x * blockDim.x + threadIdx.x;
    if (e >= E) return;
    int dst;
    if (g_idx64) dst = (int)((const long long*)ei)[(size_t)E + e];
    else         dst = ((const int*)ei)[(size_t)E + e];
    atomicAdd(&g_i[CNT + dst], 1);
}

__global__ void scan_a_kernel() {
    __shared__ int s[1024];
    int t = threadIdx.x;
    int i = blockIdx.x * 1024 + t;
    int v = (i < NN) ? g_i[CNT + i] : 0;
    s[t] = v;
    __syncthreads();
#pragma unroll
    for (int off = 1; off < 1024; off <<= 1) {
        int u = (t >= off) ? s[t - off] : 0;
        __syncthreads();
        s[t] += u;
        __syncthreads();
    }
    if (i < NN) g_i[ROWPTR + i + 1] = s[t];
    if (t == 1023) g_i[BSUM + blockIdx.x] = s[1023];
}

__global__ void scan_b_kernel() {
    __shared__ int s[128];
    int t = threadIdx.x;
    int v = (t < NB_SCAN) ? g_i[BSUM + t] : 0;
    s[t] = v;
    __syncthreads();
#pragma unroll
    for (int off = 1; off < 128; off <<= 1) {
        int u = (t >= off) ? s[t - off] : 0;
        __syncthreads();
        s[t] += u;
        __syncthreads();
    }
    if (t < NB_SCAN) g_i[BSUM + t] = s[t] - v;   // exclusive
}

__global__ void scan_c_kernel() {
    int i = blockIdx.x * blockDim.x + threadIdx.x;
    if (i < NN) g_i[ROWPTR + i + 1] += g_i[BSUM + (i >> 10)];
    if (i == 0) g_i[ROWPTR] = 0;
}

__global__ void scatter_kernel(const void* __restrict__ ei, int E) {
    int e = blockIdx.x * blockDim.x + threadIdx.x;
    if (e >= E) return;
    int src, dst;
    load_edge(ei, e, E, src, dst);
    int pos = g_i[ROWPTR + dst] + atomicAdd(&g_i[TMP + dst], 1);
    g_i[SORTED + pos] = src;
}

// ---------------------------------------------------------------------------
// Layer-1 aggregation: one warp per dst node, register accumulation,
// writes the MEAN row (scale folded in). Unroll-4 for MLP.
// ---------------------------------------------------------------------------
__global__ __launch_bounds__(256) void agg1_kernel(const float* __restrict__ x) {
    int node = (int)(((size_t)blockIdx.x * blockDim.x + threadIdx.x) >> 5);
    if (node >= NN) return;
    int lane = threadIdx.x & 31;
    int beg = g_i[ROWPTR + node];
    int end = g_i[ROWPTR + node + 1];
    const int* srt = g_i + SORTED;
    float4 acc = make_float4(0.f, 0.f, 0.f, 0.f);
    int e = beg;
    for (; e + 4 <= end; e += 4) {
        int s0 = srt[e], s1 = srt[e + 1], s2 = srt[e + 2], s3 = srt[e + 3];
        float4 v0 = ((const float4*)(x + (size_t)s0 * 128))[lane];
        float4 v1 = ((const float4*)(x + (size_t)s1 * 128))[lane];
        float4 v2 = ((const float4*)(x + (size_t)s2 * 128))[lane];
        float4 v3 = ((const float4*)(x + (size_t)s3 * 128))[lane];
        acc.x += (v0.x + v1.x) + (v2.x + v3.x);
        acc.y += (v0.y + v1.y) + (v2.y + v3.y);
        acc.z += (v0.z + v1.z) + (v2.z + v3.z);
        acc.w += (v0.w + v1.w) + (v2.w + v3.w);
    }
    for (; e < end; e++) {
        float4 v = ((const float4*)(x + (size_t)srt[e] * 128))[lane];
        acc.x += v.x; acc.y += v.y; acc.z += v.z; acc.w += v.w;
    }
    float sc = 1.0f / fmaxf((float)(end - beg), 1.0f);
    ((float4*)(g_f + AGG1 + (size_t)node * 128))[lane] =
        make_float4(acc.x * sc, acc.y * sc, acc.z * sc, acc.w * sc);
}

// ---------------------------------------------------------------------------
// GEMM 1: h = relu( agg1 @ W1_l + x @ W1_r + b1 )
//   128x128 tile, BK=16, 256 threads, 8x8 register tile via FFMA2:
//   accumulators packed along j (column pairs), b loaded as natural 64-bit
//   pairs from Bs, a lane-duplicated via mov.b64 (alu pipe, hidden).
// ---------------------------------------------------------------------------
__global__ __launch_bounds__(256) void gemm1_kernel(
    const float* __restrict__ x, const float* __restrict__ W1l,
    const float* __restrict__ b1, const float* __restrict__ W1r) {
    __shared__ float As[16][132];
    __shared__ float Bs[16][128];
    int t = threadIdx.x;
    int row0 = blockIdx.x * 128;
    int tx = t & 15, ty = t >> 4;

    unsigned long long acc[8][4];
#pragma unroll
    for (int i = 0; i < 8; i++)
#pragma unroll
        for (int jp = 0; jp < 4; jp++) acc[i][jp] = 0ull;

    const float* agg1 = g_f + AGG1;

    for (int pair = 0; pair < 2; pair++) {
        const float* A = pair ? x : agg1;
        const float* B = pair ? W1r : W1l;
        for (int kt = 0; kt < 128; kt += 16) {
#pragma unroll
            for (int l = 0; l < 2; l++) {
                int q = t + l * 256;
                int ar = q >> 2;
                int ak = (q & 3) * 4;
                int grow = row0 + ar;
                float4 v = make_float4(0.f, 0.f, 0.f, 0.f);
                if (grow < NN) v = *(const float4*)(A + (size_t)grow * 128 + kt + ak);
                As[ak + 0][ar] = v.x; As[ak + 1][ar] = v.y;
                As[ak + 2][ar] = v.z; As[ak + 3][ar] = v.w;
            }
#pragma unroll
            for (int l = 0; l < 2; l++) {
                int q = t + l * 256;
                int bk = q >> 5;
                int bn = (q & 31) * 4;
                *(float4*)&Bs[bk][bn] = *(const float4*)(B + (size_t)(kt + bk) * 128 + bn);
            }
            __syncthreads();
#pragma unroll
            for (int k = 0; k < 16; k++) {
                float4 a0 = *(float4*)&As[k][ty * 8];
                float4 a1 = *(float4*)&As[k][ty * 8 + 4];
                unsigned long long ad[8];
                ad[0] = pack2(a0.x, a0.x); ad[1] = pack2(a0.y, a0.y);
                ad[2] = pack2(a0.z, a0.z); ad[3] = pack2(a0.w, a0.w);
                ad[4] = pack2(a1.x, a1.x); ad[5] = pack2(a1.y, a1.y);
                ad[6] = pack2(a1.z, a1.z); ad[7] = pack2(a1.w, a1.w);
                const unsigned long long* bp =
                    (const unsigned long long*)&Bs[k][tx * 8];
                unsigned long long b2[4] = {bp[0], bp[1], bp[2], bp[3]};
#pragma unroll
                for (int i = 0; i < 8; i++)
#pragma unroll
                    for (int jp = 0; jp < 4; jp++) fma2(acc[i][jp], ad[i], b2[jp]);
            }
            __syncthreads();
        }
    }

    float* h = g_f + HBUF;
#pragma unroll
    for (int i = 0; i < 8; i++) {
        int r = row0 + ty * 8 + i;
        if (r < NN) {
            float v[8];
#pragma unroll
            for (int jp = 0; jp < 4; jp++) unpack2(v[2 * jp], v[2 * jp + 1], acc[i][jp]);
#pragma unroll
            for (int j = 0; j < 8; j += 4) {
                int c = tx * 8 + j;
                float4 o;
                o.x = fmaxf(v[j + 0] + b1[c + 0], 0.f);
                o.y = fmaxf(v[j + 1] + b1[c + 1], 0.f);
                o.z = fmaxf(v[j + 2] + b1[c + 2], 0.f);
                o.w = fmaxf(v[j + 3] + b1[c + 3], 0.f);
                *(float4*)(h + (size_t)r * 128 + c) = o;
            }
        }
    }
}

// ---------------------------------------------------------------------------
// GEMM 2: TR2 = h @ [W2_l | W2_r]   (M = NN, N = 128, K = 128), FFMA2.
// ---------------------------------------------------------------------------
__global__ __launch_bounds__(256) void gemm2_kernel(
    const float* __restrict__ W2l, const float* __restrict__ W2r) {
    __shared__ float As[16][132];
    __shared__ float Bs[16][128];
    int t = threadIdx.x;
    int row0 = blockIdx.x * 128;
    int tx = t & 15, ty = t >> 4;

    unsigned long long acc[8][4];
#pragma unroll
    for (int i = 0; i < 8; i++)
#pragma unroll
        for (int jp = 0; jp < 4; jp++) acc[i][jp] = 0ull;

    const float* h = g_f + HBUF;

    for (int kt = 0; kt < 128; kt += 16) {
#pragma unroll
        for (int l = 0; l < 2; l++) {
            int q = t + l * 256;
            int ar = q >> 2;
            int ak = (q & 3) * 4;
            int grow = row0 + ar;
            float4 v = make_float4(0.f, 0.f, 0.f, 0.f);
            if (grow < NN) v = *(const float4*)(h + (size_t)grow * 128 + kt + ak);
            As[ak + 0][ar] = v.x; As[ak + 1][ar] = v.y;
            As[ak + 2][ar] = v.z; As[ak + 3][ar] = v.w;
        }
#pragma unroll
        for (int l = 0; l < 2; l++) {
            int q = t + l * 256;
            int bk = q >> 5;
            int bn = (q & 31) * 4;
            float4 v;
            if (bn < 64) v = *(const float4*)(W2l + (size_t)(kt + bk) * 64 + bn);
            else         v = *(const float4*)(W2r + (size_t)(kt + bk) * 64 + (bn - 64));
            *(float4*)&Bs[bk][bn] = v;
        }
        __syncthreads();
#pragma unroll
        for (int k = 0; k < 16; k++) {
            float4 a0 = *(float4*)&As[k][ty * 8];
            float4 a1 = *(float4*)&As[k][ty * 8 + 4];
            unsigned long long ad[8];
            ad[0] = pack2(a0.x, a0.x); ad[1] = pack2(a0.y, a0.y);
            ad[2] = pack2(a0.z, a0.z); ad[3] = pack2(a0.w, a0.w);
            ad[4] = pack2(a1.x, a1.x); ad[5] = pack2(a1.y, a1.y);
            ad[6] = pack2(a1.z, a1.z); ad[7] = pack2(a1.w, a1.w);
            const unsigned long long* bp =
                (const unsigned long long*)&Bs[k][tx * 8];
            unsigned long long b2[4] = {bp[0], bp[1], bp[2], bp[3]};
#pragma unroll
            for (int i = 0; i < 8; i++)
#pragma unroll
                for (int jp = 0; jp < 4; jp++) fma2(acc[i][jp], ad[i], b2[jp]);
        }
        __syncthreads();
    }

    float* tr2 = g_f + TR2;
#pragma unroll
    for (int i = 0; i < 8; i++) {
        int r = row0 + ty * 8 + i;
        if (r < NN) {
            float v[8];
#pragma unroll
            for (int jp = 0; jp < 4; jp++) unpack2(v[2 * jp], v[2 * jp + 1], acc[i][jp]);
#pragma unroll
            for (int j = 0; j < 8; j += 4) {
                int c = tx * 8 + j;
                *(float4*)(tr2 + (size_t)r * 128 + c) =
                    make_float4(v[j], v[j + 1], v[j + 2], v[j + 3]);
            }
        }
    }
}

// ---------------------------------------------------------------------------
// Layer-2 aggregation fused with epilogue:
//   out[i] = mean_{j in N(i)} t2[j] + b2 + r2[i]
// ---------------------------------------------------------------------------
__global__ __launch_bounds__(256) void agg2_kernel(const float* __restrict__ b2,
                                                   float* __restrict__ out) {
    int node = (int)(((size_t)blockIdx.x * blockDim.x + threadIdx.x) >> 5);
    if (node >= NN) return;
    int lane = threadIdx.x & 31;
    int beg = g_i[ROWPTR + node];
    int end = g_i[ROWPTR + node + 1];
    const int* srt = g_i + SORTED;
    const float* t2 = g_f + TR2;
    float2 acc = make_float2(0.f, 0.f);
    int e = beg;
    for (; e + 4 <= end; e += 4) {
        int s0 = srt[e], s1 = srt[e + 1], s2 = srt[e + 2], s3 = srt[e + 3];
        float2 v0 = ((const float2*)(t2 + (size_t)s0 * 128))[lane];
        float2 v1 = ((const float2*)(t2 + (size_t)s1 * 128))[lane];
        float2 v2 = ((const float2*)(t2 + (size_t)s2 * 128))[lane];
        float2 v3 = ((const float2*)(t2 + (size_t)s3 * 128))[lane];
        acc.x += (v0.x + v1.x) + (v2.x + v3.x);
        acc.y += (v0.y + v1.y) + (v2.y + v3.y);
    }
    for (; e < end; e++) {
        float2 v = ((const float2*)(t2 + (size_t)srt[e] * 128))[lane];
        acc.x += v.x; acc.y += v.y;
    }
    float sc = 1.0f / fmaxf((float)(end - beg), 1.0f);
    float2 r = ((const float2*)(t2 + (size_t)node * 128 + 64))[lane];
    float2 bb = ((const float2*)b2)[lane];
    float2 o;
    o.x = acc.x * sc + bb.x + r.x;
    o.y = acc.y * sc + bb.y + r.y;
    ((float2*)(out + (size_t)node * 64))[lane] = o;
}

extern "C" void kernel_launch(void* const* d_in, const int* in_sizes, int n_in,
                              void* d_out, int out_size) {
    const float* x   = (const float*)d_in[0];
    const float* W1l = (const float*)d_in[1];
    const float* b1  = (const float*)d_in[2];
    const float* W1r = (const float*)d_in[3];
    const float* W2l = (const float*)d_in[4];
    const float* b2  = (const float*)d_in[5];
    const float* W2r = (const float*)d_in[6];
    const void*  ei  = d_in[7];
    int E = in_sizes[7] / 2;
    if (E > EMAX) E = EMAX;
    float* out = (float*)d_out;

    detect_kernel<<<1, 32>>>(ei);
    zero_int_kernel<<<(2 * NN + 255) / 256, 256>>>();
    hist_kernel<<<(E + 255) / 256, 256>>>(ei, E);
    scan_a_kernel<<<NB_SCAN, 1024>>>();
    scan_b_kernel<<<1, 128>>>();
    scan_c_kernel<<<(NN + 255) / 256, 256>>>();
    scatter_kernel<<<(E + 255) / 256, 256>>>(ei, E);

    agg1_kernel<<<(NN * 32 + 255) / 256, 256>>>(x);
    gemm1_kernel<<<(NN + 127) / 128, 256>>>(x, W1l, b1, W1r);
    gemm2_kernel<<<(NN + 127) / 128, 256>>>(W2l, W2r);
    agg2_kernel<<<(NN * 32 + 255) / 256, 256>>>(b2, out);
}